// round 9
// baseline (speedup 1.0000x reference)
#include <cuda_runtime.h>
#include <cuda_fp16.h>
#include <cstdint>
#include <cstddef>

// ============================================================================
// Problem constants
// ============================================================================
#define IN_F   4096
#define OUT_F  4096
#define M_TOT  8192            // 4 * 2048 flattened

// GEMM tiling: CTA 256(M) x 128(N), BK=64, 3-stage cp.async pipeline
#define BK          64
#define K_ITERS     (IN_F / BK)              // 64
#define STAGES      3
#define A_BYTES     (256 * 128)              // 256 rows x 128 B = 32 KB
#define B_BYTES     (128 * 128)              // 16 KB
#define STAGE_BYTES (A_BYTES + B_BYTES)      // 48 KB
#define SMEM_TOTAL  (1024 + STAGES * STAGE_BYTES)   // 148480 B
#define GEMM_THREADS 256

// ============================================================================
// Device scratch (__device__ globals: the allowed scratch mechanism)
// ============================================================================
static __device__ __half g_Xh[(size_t)M_TOT * IN_F];   // 64 MB: x in fp16
static __device__ __half g_Wt[(size_t)OUT_F * IN_F];   // 32 MB: W^T fp16, row n K-major

__constant__ float c_code[16] = {
    -6.f, -4.f, -3.f, -2.f, -1.5f, -1.f, -0.5f, -0.0f,
     0.f,  0.5f, 1.f,  1.5f,  2.f,   3.f,  4.f,  6.f};

// ============================================================================
// Helpers
// ============================================================================
__device__ __forceinline__ uint32_t smem_u32(const void* p) {
    return (uint32_t)__cvta_generic_to_shared(p);
}

__device__ __forceinline__ void cp_async16(uint32_t dst_smem, const void* src_gmem) {
    asm volatile("cp.async.cg.shared.global [%0], [%1], 16;\n"
                 :: "r"(dst_smem), "l"(src_gmem));
}
__device__ __forceinline__ void cp_async_commit() {
    asm volatile("cp.async.commit_group;\n" ::: "memory");
}
template <int N>
__device__ __forceinline__ void cp_async_wait() {
    asm volatile("cp.async.wait_group %0;\n" :: "n"(N) : "memory");
}

// SW128 swizzle: XOR bits [6:4] with bits [9:7]  (tile base must be 1024B aligned)
__device__ __forceinline__ uint32_t sw128(uint32_t off) {
    return off ^ ((off >> 3) & 0x70);
}

__device__ __forceinline__ void ldsm_x4(uint32_t& r0, uint32_t& r1,
                                        uint32_t& r2, uint32_t& r3, uint32_t addr) {
    asm volatile("ldmatrix.sync.aligned.m8n8.x4.shared.b16 {%0,%1,%2,%3}, [%4];"
                 : "=r"(r0), "=r"(r1), "=r"(r2), "=r"(r3) : "r"(addr));
}

__device__ __forceinline__ void mma16816(float* d, const uint32_t* a, const uint32_t* b) {
    asm volatile(
        "mma.sync.aligned.m16n8k16.row.col.f32.f16.f16.f32 "
        "{%0,%1,%2,%3}, {%4,%5,%6,%7}, {%8,%9}, {%0,%1,%2,%3};"
        : "+f"(d[0]), "+f"(d[1]), "+f"(d[2]), "+f"(d[3])
        : "r"(a[0]), "r"(a[1]), "r"(a[2]), "r"(a[3]), "r"(b[0]), "r"(b[1]));
}

// Streaming 8-byte store (evict-first): output is write-once, never re-read;
// keep it from evicting the L2-resident g_Wt working set.
__device__ __forceinline__ void stg_cs_v2(float* p, float x, float y) {
    asm volatile("st.global.cs.v2.f32 [%0], {%1, %2};" :: "l"(p), "f"(x), "f"(y)
                 : "memory");
}

// ============================================================================
// Kernel 1: x fp32 -> fp16   (one thread per 4 floats, exact grid)
// ============================================================================
__global__ void __launch_bounds__(256) k_convert_x(const float* __restrict__ x) {
    size_t i = (size_t)blockIdx.x * blockDim.x + threadIdx.x;
    float4 v = reinterpret_cast<const float4*>(x)[i];
    __half2* dst = reinterpret_cast<__half2*>(g_Xh) + 2 * i;
    dst[0] = __floats2half2_rn(v.x, v.y);
    dst[1] = __floats2half2_rn(v.z, v.w);
}

// ============================================================================
// Kernel 2: dequant packed int32 -> W^T fp16 (row n, K contiguous)
// qweight[r][n], nibble j -> k = r*8 + j ; group g = k/128 = r/16
// ============================================================================
__global__ void __launch_bounds__(256) k_dequant(const int* __restrict__ qw,
                                                 const float* __restrict__ s1,
                                                 const float* __restrict__ s2) {
    int idx = blockIdx.x * blockDim.x + threadIdx.x;   // (IN_F/8)*OUT_F threads
    int n = idx & (OUT_F - 1);
    int r = idx >> 12;                                  // OUT_F = 4096 = 2^12
    int v = qw[idx];                                    // qw[r*OUT_F + n]
    int g = r >> 4;
    float sp = s1[g * OUT_F + n];                       // scale for codes >= 0
    float sn = s2[g * OUT_F + n];                       // scale for codes <  0
    __half h[8];
#pragma unroll
    for (int j = 0; j < 8; j++) {
        int q = (v >> (4 * j)) & 15;
        float c = c_code[q];
        // matches jnp.where(w >= 0, ...): -0.0f >= 0.f is true -> uses s1
        h[j] = __float2half_rn(c * (c >= 0.f ? sp : sn));
    }
    *reinterpret_cast<uint4*>(&g_Wt[(size_t)n * IN_F + (r << 3)]) =
        *reinterpret_cast<const uint4*>(h);
}

// ============================================================================
// Kernel 3: HMMA GEMM  (mma.sync.m16n8k16, cp.async 3-stage pipeline)
//   A = g_Xh [M_TOT, IN_F] K-major ; B = g_Wt [OUT_F, IN_F] K-major (= B col-major)
//   out = A @ B^T + bias (fp32)
// CTA tile 256x128. Warp layout: 4 (M) x 2 (N); warp tile 64 x 64.
// ============================================================================
__device__ __forceinline__ void load_stage(int kiter, int stage, int m0, int n0,
                                           uint32_t sbase, int tid) {
    int k0 = kiter * BK;
    uint32_t sA = sbase + stage * STAGE_BYTES;
    uint32_t sB = sA + A_BYTES;
    const __half* Xh = g_Xh;
    const __half* Wt = g_Wt;
    // A: 2048 16B-chunks (256 rows), iterations 0..7
#pragma unroll
    for (int i = 0; i < 8; i++) {
        int c   = tid + i * GEMM_THREADS;   // 0..2047
        int row = c >> 3;                   // 0..255
        int cc  = c & 7;
        uint32_t sw = sw128((uint32_t)(row * 128 + cc * 16));
        cp_async16(sA + sw, Xh + (size_t)(m0 + row) * IN_F + k0 + cc * 8);
    }
    // B: 1024 16B-chunks (128 rows), iterations 0..3
#pragma unroll
    for (int i = 0; i < 4; i++) {
        int c   = tid + i * GEMM_THREADS;   // 0..1023
        int row = c >> 3;                   // 0..127
        int cc  = c & 7;
        uint32_t sw = sw128((uint32_t)(row * 128 + cc * 16));
        cp_async16(sB + sw, Wt + (size_t)(n0 + row) * IN_F + k0 + cc * 8);
    }
}

__global__ void __launch_bounds__(GEMM_THREADS, 1)
k_gemm(const float* __restrict__ bias, float* __restrict__ out) {
    extern __shared__ char smem_raw[];
    uint32_t sbase = (smem_u32(smem_raw) + 1023u) & ~1023u;

    int tid = threadIdx.x;
    int lid = tid & 31;
    int wid = tid >> 5;
    int wm  = wid & 3;          // 4 M-warps, 64 rows each
    int wn  = wid >> 2;         // 2 N-warps, 64 cols each
    int m0  = blockIdx.y * 256;
    int n0  = blockIdx.x * 128;

    float acc[4][8][4];         // [mtile 16r][ntile 8c][frag]
#pragma unroll
    for (int i = 0; i < 4; i++)
#pragma unroll
        for (int j = 0; j < 8; j++)
#pragma unroll
            for (int q = 0; q < 4; q++) acc[i][j][q] = 0.f;

    // Pipeline prologue
#pragma unroll
    for (int s = 0; s < STAGES - 1; s++) {
        load_stage(s, s, m0, n0, sbase, tid);
        cp_async_commit();
    }

    // Per-lane ldmatrix address components (within-tile)
    int g = lid >> 3;           // 8-lane address group = matrix index
    // A: matrices ordered (m0-7,k0) (m8-15,k0) (m0-7,k8) (m8-15,k8)
    int a_row_in = wm * 64 + (g & 1) * 8 + (lid & 7);   // + mt*16
    int a_col    = (g >> 1) * 8;                        // + ks*16
    // B: matrices ordered (n0-7,k0) (n0-7,k8) (n8-15,k0) (n8-15,k8)
    int b_row_in = wn * 64 + (g >> 1) * 8 + (lid & 7);  // + np*16
    int b_col    = (g & 1) * 8;                         // + ks*16

    for (int k = 0; k < K_ITERS; k++) {
        cp_async_wait<STAGES - 2>();     // stage k%STAGES data resident
        __syncthreads();

        int kn = k + STAGES - 1;
        if (kn < K_ITERS) load_stage(kn, kn % STAGES, m0, n0, sbase, tid);
        cp_async_commit();               // keep group accounting uniform

        uint32_t sA = sbase + (k % STAGES) * STAGE_BYTES;
        uint32_t sB = sA + A_BYTES;

#pragma unroll
        for (int ks = 0; ks < 4; ks++) {
            uint32_t a[4][4];
#pragma unroll
            for (int mt = 0; mt < 4; mt++) {
                uint32_t addr = sA + sw128((uint32_t)(
                    (a_row_in + mt * 16) * 128 + (ks * 16 + a_col) * 2));
                ldsm_x4(a[mt][0], a[mt][1], a[mt][2], a[mt][3], addr);
            }
            uint32_t b[8][2];
#pragma unroll
            for (int np = 0; np < 4; np++) {
                uint32_t addr = sB + sw128((uint32_t)(
                    (b_row_in + np * 16) * 128 + (ks * 16 + b_col) * 2));
                ldsm_x4(b[np * 2][0], b[np * 2][1], b[np * 2 + 1][0],
                        b[np * 2 + 1][1], addr);
            }
#pragma unroll
            for (int mt = 0; mt < 4; mt++)
#pragma unroll
                for (int nt = 0; nt < 8; nt++)
                    mma16816(acc[mt][nt], a[mt], b[nt]);
        }
    }

    // Epilogue: acc frag layout: c0,c1 -> (row l/4,   col (l%4)*2 +0/1)
    //                            c2,c3 -> (row l/4+8, same cols)
    int er = lid >> 2;
    int ec = (lid & 3) * 2;
#pragma unroll
    for (int nt = 0; nt < 8; nt++) {
        int col = n0 + wn * 64 + nt * 8 + ec;
        float2 bv = *reinterpret_cast<const float2*>(&bias[col]);
#pragma unroll
        for (int mt = 0; mt < 4; mt++) {
            int row = m0 + wm * 64 + mt * 16 + er;
            stg_cs_v2(&out[(size_t)row * OUT_F + col],
                      acc[mt][nt][0] + bv.x, acc[mt][nt][1] + bv.y);
            stg_cs_v2(&out[(size_t)(row + 8) * OUT_F + col],
                      acc[mt][nt][2] + bv.x, acc[mt][nt][3] + bv.y);
        }
    }
}

// ============================================================================
// Launch
// ============================================================================
extern "C" void kernel_launch(void* const* d_in, const int* in_sizes, int n_in,
                              void* d_out, int out_size) {
    const float* x    = (const float*)d_in[0];
    const int*   qw   = (const int*)d_in[1];
    const float* s1   = (const float*)d_in[2];
    const float* s2   = (const float*)d_in[3];
    const float* bias = (const float*)d_in[4];
    float*       out  = (float*)d_out;

    // 1) x -> fp16
    k_convert_x<<<(M_TOT * (size_t)IN_F / 4) / 256, 256>>>(x);

    // 2) dequant -> W^T fp16
    k_dequant<<<((IN_F / 8) * OUT_F) / 256, 256>>>(qw, s1, s2);

    // 3) GEMM (set attribute unconditionally: no static guards allowed)
    cudaFuncSetAttribute(k_gemm, cudaFuncAttributeMaxDynamicSharedMemorySize,
                         SMEM_TOTAL);
    dim3 grid(OUT_F / 128, M_TOT / 256);   // (32, 32) = 1024 CTAs
    k_gemm<<<grid, GEMM_THREADS, SMEM_TOTAL>>>(bias, out);
}

// round 16
// speedup vs baseline: 1.1022x; 1.1022x over previous
#include <cuda_runtime.h>
#include <cuda_fp16.h>
#include <cstdint>
#include <cstddef>

// ============================================================================
// Problem constants
// ============================================================================
#define IN_F   4096
#define OUT_F  4096
#define M_TOT  8192            // 4 * 2048 flattened

// GEMM tiling: CTA 128x128, 4 warps (warp tile 64x64), BK=64, 3-stage cp.async
#define BK          64
#define K_ITERS     (IN_F / BK)              // 64
#define STAGES      3
#define A_BYTES     (128 * 128)              // 16 KB
#define B_BYTES     (128 * 128)              // 16 KB
#define STAGE_BYTES (A_BYTES + B_BYTES)      // 32 KB
#define SMEM_TOTAL  (1024 + STAGES * STAGE_BYTES)   // 99328 B; x2 CTAs = 198.7 KB
#define GEMM_THREADS 128

// ============================================================================
// Device scratch (__device__ globals: the allowed scratch mechanism)
// ============================================================================
static __device__ __half g_Xh[(size_t)M_TOT * IN_F];   // 64 MB: x in fp16
static __device__ __half g_Wt[(size_t)OUT_F * IN_F];   // 32 MB: W^T fp16, row n K-major

__constant__ float c_code[16] = {
    -6.f, -4.f, -3.f, -2.f, -1.5f, -1.f, -0.5f, -0.0f,
     0.f,  0.5f, 1.f,  1.5f,  2.f,   3.f,  4.f,  6.f};

// ============================================================================
// Helpers
// ============================================================================
__device__ __forceinline__ uint32_t smem_u32(const void* p) {
    return (uint32_t)__cvta_generic_to_shared(p);
}

__device__ __forceinline__ void cp_async16(uint32_t dst_smem, const void* src_gmem) {
    asm volatile("cp.async.cg.shared.global [%0], [%1], 16;\n"
                 :: "r"(dst_smem), "l"(src_gmem));
}
__device__ __forceinline__ void cp_async_commit() {
    asm volatile("cp.async.commit_group;\n" ::: "memory");
}
template <int N>
__device__ __forceinline__ void cp_async_wait() {
    asm volatile("cp.async.wait_group %0;\n" :: "n"(N) : "memory");
}

// SW128 swizzle: XOR bits [6:4] with bits [9:7]  (tile base must be 1024B aligned)
__device__ __forceinline__ uint32_t sw128(uint32_t off) {
    return off ^ ((off >> 3) & 0x70);
}

__device__ __forceinline__ void ldsm_x4(uint32_t& r0, uint32_t& r1,
                                        uint32_t& r2, uint32_t& r3, uint32_t addr) {
    asm volatile("ldmatrix.sync.aligned.m8n8.x4.shared.b16 {%0,%1,%2,%3}, [%4];"
                 : "=r"(r0), "=r"(r1), "=r"(r2), "=r"(r3) : "r"(addr));
}

__device__ __forceinline__ void mma16816(float* d, const uint32_t* a, const uint32_t* b) {
    asm volatile(
        "mma.sync.aligned.m16n8k16.row.col.f32.f16.f16.f32 "
        "{%0,%1,%2,%3}, {%4,%5,%6,%7}, {%8,%9}, {%0,%1,%2,%3};"
        : "+f"(d[0]), "+f"(d[1]), "+f"(d[2]), "+f"(d[3])
        : "r"(a[0]), "r"(a[1]), "r"(a[2]), "r"(a[3]), "r"(b[0]), "r"(b[1]));
}

// Streaming 8-byte store (evict-first): output is write-once, never re-read;
// keep it from evicting the L2-resident g_Wt working set.
__device__ __forceinline__ void stg_cs_v2(float* p, float x, float y) {
    asm volatile("st.global.cs.v2.f32 [%0], {%1, %2};" :: "l"(p), "f"(x), "f"(y)
                 : "memory");
}

// ============================================================================
// Kernel 1: x fp32 -> fp16   (one thread per 4 floats, exact grid)
// ============================================================================
__global__ void __launch_bounds__(256) k_convert_x(const float* __restrict__ x) {
    size_t i = (size_t)blockIdx.x * blockDim.x + threadIdx.x;
    float4 v = reinterpret_cast<const float4*>(x)[i];
    __half2* dst = reinterpret_cast<__half2*>(g_Xh) + 2 * i;
    dst[0] = __floats2half2_rn(v.x, v.y);
    dst[1] = __floats2half2_rn(v.z, v.w);
}

// ============================================================================
// Kernel 2: dequant packed int32 -> W^T fp16 (row n, K contiguous)
// qweight[r][n], nibble j -> k = r*8 + j ; group g = k/128 = r/16
// ============================================================================
__global__ void __launch_bounds__(256) k_dequant(const int* __restrict__ qw,
                                                 const float* __restrict__ s1,
                                                 const float* __restrict__ s2) {
    int idx = blockIdx.x * blockDim.x + threadIdx.x;   // (IN_F/8)*OUT_F threads
    int n = idx & (OUT_F - 1);
    int r = idx >> 12;                                  // OUT_F = 4096 = 2^12
    int v = qw[idx];                                    // qw[r*OUT_F + n]
    int g = r >> 4;
    float sp = s1[g * OUT_F + n];                       // scale for codes >= 0
    float sn = s2[g * OUT_F + n];                       // scale for codes <  0
    __half h[8];
#pragma unroll
    for (int j = 0; j < 8; j++) {
        int q = (v >> (4 * j)) & 15;
        float c = c_code[q];
        // matches jnp.where(w >= 0, ...): -0.0f >= 0.f is true -> uses s1
        h[j] = __float2half_rn(c * (c >= 0.f ? sp : sn));
    }
    *reinterpret_cast<uint4*>(&g_Wt[(size_t)n * IN_F + (r << 3)]) =
        *reinterpret_cast<const uint4*>(h);
}

// ============================================================================
// Kernel 3: HMMA GEMM  (mma.sync.m16n8k16, cp.async 3-stage pipeline)
//   A = g_Xh [M_TOT, IN_F] K-major ; B = g_Wt [OUT_F, IN_F] K-major (= B col-major)
//   out = A @ B^T + bias (fp32)
// CTA tile 128x128, 4 warps in 2(M) x 2(N); warp tile 64 x 64.
// 2 CTAs/SM preserve cross-CTA overlap while cutting LDSM traffic per FLOP.
// ============================================================================
__device__ __forceinline__ void load_stage(int kiter, int stage, int m0, int n0,
                                           uint32_t sbase, int tid) {
    int k0 = kiter * BK;
    uint32_t sA = sbase + stage * STAGE_BYTES;
    uint32_t sB = sA + A_BYTES;
    const __half* Xh = g_Xh;
    const __half* Wt = g_Wt;
#pragma unroll
    for (int i = 0; i < 8; i++) {
        int c   = tid + i * GEMM_THREADS;   // 0..1023
        int row = c >> 3;                   // 0..127
        int cc  = c & 7;                    // 16B chunk within the 128B row
        uint32_t sw = sw128((uint32_t)(row * 128 + cc * 16));
        cp_async16(sA + sw, Xh + (size_t)(m0 + row) * IN_F + k0 + cc * 8);
        cp_async16(sB + sw, Wt + (size_t)(n0 + row) * IN_F + k0 + cc * 8);
    }
}

__global__ void __launch_bounds__(GEMM_THREADS, 2)
k_gemm(const float* __restrict__ bias, float* __restrict__ out) {
    extern __shared__ char smem_raw[];
    uint32_t sbase = (smem_u32(smem_raw) + 1023u) & ~1023u;

    int tid = threadIdx.x;
    int lid = tid & 31;
    int wid = tid >> 5;         // 0..3
    int wm  = wid & 1;          // 2 M-warps, 64 rows each
    int wn  = wid >> 1;         // 2 N-warps, 64 cols each
    int m0  = blockIdx.y * 128;
    int n0  = blockIdx.x * 128;

    float acc[4][8][4];         // [mtile 16r][ntile 8c][frag]
#pragma unroll
    for (int i = 0; i < 4; i++)
#pragma unroll
        for (int j = 0; j < 8; j++)
#pragma unroll
            for (int q = 0; q < 4; q++) acc[i][j][q] = 0.f;

    // Pipeline prologue
#pragma unroll
    for (int s = 0; s < STAGES - 1; s++) {
        load_stage(s, s, m0, n0, sbase, tid);
        cp_async_commit();
    }

    // Per-lane ldmatrix address components (within-tile)
    int g = lid >> 3;           // 8-lane address group = matrix index
    // A: matrices ordered (m0-7,k0) (m8-15,k0) (m0-7,k8) (m8-15,k8)
    int a_row_in = wm * 64 + (g & 1) * 8 + (lid & 7);   // + mt*16
    int a_col    = (g >> 1) * 8;                        // + ks*16
    // B: matrices ordered (n0-7,k0) (n0-7,k8) (n8-15,k0) (n8-15,k8)
    int b_row_in = wn * 64 + (g >> 1) * 8 + (lid & 7);  // + np*16
    int b_col    = (g & 1) * 8;                         // + ks*16

    for (int k = 0; k < K_ITERS; k++) {
        cp_async_wait<STAGES - 2>();     // stage k%STAGES data resident
        __syncthreads();

        int kn = k + STAGES - 1;
        if (kn < K_ITERS) load_stage(kn, kn % STAGES, m0, n0, sbase, tid);
        cp_async_commit();               // keep group accounting uniform

        uint32_t sA = sbase + (k % STAGES) * STAGE_BYTES;
        uint32_t sB = sA + A_BYTES;

#pragma unroll
        for (int ks = 0; ks < 4; ks++) {
            uint32_t a[4][4];
#pragma unroll
            for (int mt = 0; mt < 4; mt++) {
                uint32_t addr = sA + sw128((uint32_t)(
                    (a_row_in + mt * 16) * 128 + (ks * 16 + a_col) * 2));
                ldsm_x4(a[mt][0], a[mt][1], a[mt][2], a[mt][3], addr);
            }
            uint32_t b[8][2];
#pragma unroll
            for (int np = 0; np < 4; np++) {
                uint32_t addr = sB + sw128((uint32_t)(
                    (b_row_in + np * 16) * 128 + (ks * 16 + b_col) * 2));
                ldsm_x4(b[np * 2][0], b[np * 2][1], b[np * 2 + 1][0],
                        b[np * 2 + 1][1], addr);
            }
#pragma unroll
            for (int mt = 0; mt < 4; mt++)
#pragma unroll
                for (int nt = 0; nt < 8; nt++)
                    mma16816(acc[mt][nt], a[mt], b[nt]);
        }
    }

    // Epilogue: acc frag layout: c0,c1 -> (row l/4,   col (l%4)*2 +0/1)
    //                            c2,c3 -> (row l/4+8, same cols)
    int er = lid >> 2;
    int ec = (lid & 3) * 2;
#pragma unroll
    for (int nt = 0; nt < 8; nt++) {
        int col = n0 + wn * 64 + nt * 8 + ec;
        float2 bv = *reinterpret_cast<const float2*>(&bias[col]);
#pragma unroll
        for (int mt = 0; mt < 4; mt++) {
            int row = m0 + wm * 64 + mt * 16 + er;
            stg_cs_v2(&out[(size_t)row * OUT_F + col],
                      acc[mt][nt][0] + bv.x, acc[mt][nt][1] + bv.y);
            stg_cs_v2(&out[(size_t)(row + 8) * OUT_F + col],
                      acc[mt][nt][2] + bv.x, acc[mt][nt][3] + bv.y);
        }
    }
}

// ============================================================================
// Launch
// ============================================================================
extern "C" void kernel_launch(void* const* d_in, const int* in_sizes, int n_in,
                              void* d_out, int out_size) {
    const float* x    = (const float*)d_in[0];
    const int*   qw   = (const int*)d_in[1];
    const float* s1   = (const float*)d_in[2];
    const float* s2   = (const float*)d_in[3];
    const float* bias = (const float*)d_in[4];
    float*       out  = (float*)d_out;

    // 1) x -> fp16
    k_convert_x<<<(M_TOT * (size_t)IN_F / 4) / 256, 256>>>(x);

    // 2) dequant -> W^T fp16
    k_dequant<<<((IN_F / 8) * OUT_F) / 256, 256>>>(qw, s1, s2);

    // 3) GEMM (set attribute unconditionally: no static guards allowed)
    cudaFuncSetAttribute(k_gemm, cudaFuncAttributeMaxDynamicSharedMemorySize,
                         SMEM_TOTAL);
    dim3 grid(OUT_F / 128, M_TOT / 128);   // (32, 64) = 2048 CTAs
    k_gemm<<<grid, GEMM_THREADS, SMEM_TOTAL>>>(bias, out);
}